// round 11
// baseline (speedup 1.0000x reference)
#include <cuda_runtime.h>

// Inverse discrete Hough transform, round 11 = round 10 (pattern-sorted
// group gather) + manual multi-angle unroll inside each pattern group:
// loads of U angles are issued back-to-back BEFORE any dependent add, so
// 4-8 independent LDG.128 are in flight per iteration (fixes the dynamic-
// trip-count pipelining gap that held R10 at ~55% of its LDG floor).
// Pass B: angles 0..44 & 135..179, strips along y -> pBT[x*256+y][nc]
// Pass A: angles 45..134, strips along x, += pBT fold, -> out.

#define NA 180
#define NR 400
#define NC 256
#define OH 256
#define OW 256
#define AR (NA * NR)      // 72000
#define HW (OH * OW)      // 65536
#define NS4 16384         // strips of 4 px per pass
#define TS 96             // u32 per strip table: 4 (cum counts) + 90 offs + pad

typedef unsigned long long ull;

__device__ float  g_accT[AR * NC];                 // 73.7 MB: [a*400+r][nc]
__device__ float2 g_trig[NA];
__device__ unsigned g_tabA[(size_t)NS4 * TS];      // sorted per-strip tables
__device__ unsigned g_tabB[(size_t)NS4 * TS];
__device__ ull    g_pBT[(size_t)HW * 128];         // pass-B partial [x*256+y][nc/2]

__device__ __forceinline__ ull fadd2(ull a, ull b) {
    ull r;
    asm("add.rn.f32x2 %0, %1, %2;" : "=l"(r) : "l"(a), "l"(b));
    return r;
}
__device__ __forceinline__ float u64lo(ull u) {
    float a, b; asm("mov.b64 {%0,%1}, %2;" : "=f"(a), "=f"(b) : "l"(u)); return a;
}
__device__ __forceinline__ float u64hi(ull u) {
    float a, b; asm("mov.b64 {%0,%1}, %2;" : "=f"(a), "=f"(b) : "l"(u)); return b;
}
#define LDG2(v0, v1, addr)                                             \
    asm("ld.global.nc.v2.u64 {%0,%1}, [%2];"                           \
        : "=l"(v0), "=l"(v1) : "l"(addr))

__global__ void k_trig() {
    int a = threadIdx.x;
    if (a < NA) {
        // f32 theta (rn multiply), then correctly-rounded f32 cos/sin via
        // double (immune to fast-math; matches the JAX reference bit-exactly).
        float t = __fmul_rn((float)a, (float)(3.14159265358979323846 / 180.0));
        double td = (double)t;
        g_trig[a] = make_float2((float)cos(td), (float)sin(td));
    }
}

// 32x32 tiled transpose of acc[256][72000] -> g_accT[72000][256]
__global__ void k_transpose(const float* __restrict__ in) {
    __shared__ float tile[32][33];
    int tx = threadIdx.x, ty = threadIdx.y;           // 32 x 8
    int ar = blockIdx.x * 32 + tx;
#pragma unroll
    for (int k = 0; k < 4; k++)
        tile[ty + k * 8][tx] = in[(size_t)(blockIdx.y * 32 + ty + k * 8) * AR + ar];
    __syncthreads();
    int nc2 = blockIdx.y * 32 + tx;
#pragma unroll
    for (int k = 0; k < 4; k++)
        g_accT[(size_t)(blockIdx.x * 32 + ty + k * 8) * NC + nc2] = tile[tx][ty + k * 8];
}

// Table builder (both passes in one launch; pass = blockIdx.y).
// One warp per strip: exact offsets, pattern code (0 flat; 1..7 asc;
// 9..15 desc), then the 90 base offsets sorted by code + cumulative counts.
__global__ void k_tab() {
    int pass = blockIdx.y;               // 0 = A (x-strips), 1 = B (y-strips)
    int tid = threadIdx.x, w = tid >> 5, l = tid & 31;
    int s = blockIdx.x * 8 + w;
    unsigned* tabw = ((pass == 0) ? g_tabA : g_tabB) + (size_t)s * TS;
    int line = s >> 6, q0 = (s & 63) << 2;

    unsigned codev[3], basev[3];
#pragma unroll
    for (int i = 0; i < 3; i++) {
        int ar = i * 32 + l;
        codev[i] = 0xFFFFu;
        if (ar < 90) {
            int a = (pass == 0) ? (45 + ar) : (ar < 45 ? ar : ar + 90);
            float2 cs = g_trig[a];
            unsigned off[4];
#pragma unroll
            for (int p = 0; p < 4; p++) {
                int x = (pass == 0) ? (q0 + p) : line;
                int y = (pass == 0) ? line : (q0 + p);
                // exact reference arithmetic: rn(rn(xc*c)+rn(yc*s)), rne round
                float sum = __fadd_rn(__fmul_rn((float)(x - 128), cs.x),
                                      __fmul_rn((float)(y - 128), cs.y));
                off[p] = (unsigned)(a * NR + __float2int_rn(sum) + 200) << 10;
            }
            int d1 = ((int)(off[1] - off[0])) >> 10;
            int d2 = ((int)(off[2] - off[0])) >> 10;
            int d3 = ((int)(off[3] - off[0])) >> 10;
            int b1 = d1 != 0, b2 = d2 != d1, b3 = d3 != d2;
            int bits = b1 | (b2 << 1) | (b3 << 2);
            int neg = (d1 < 0) | (d2 < 0) | (d3 < 0);
            codev[i] = (bits == 0) ? 0u : (unsigned)(bits + (neg ? 8 : 0));
            basev[i] = off[0];
        }
    }

    unsigned lmlt = (1u << l) - 1u;
    int cnt = 0;
    unsigned cword[4] = {0, 0, 0, 0};
#pragma unroll
    for (int c = 0; c < 16; c++) {
#pragma unroll
        for (int i = 0; i < 3; i++) {
            bool v = (codev[i] == (unsigned)c);
            unsigned m = __ballot_sync(0xFFFFFFFFu, v);
            if (v) tabw[4 + cnt + __popc(m & lmlt)] = basev[i];
            cnt += __popc(m);
        }
        cword[c >> 2] |= (unsigned)cnt << ((c & 3) * 8);
    }
    if (l == 0) {
        tabw[0] = cword[0]; tabw[1] = cword[1];
        tabw[2] = cword[2]; tabw[3] = cword[3];
    }
}

// loads for one angle: K distinct rows at addr + S*1024*{0..K-1}, 2 LDG2/row
template <int K, int S>
__device__ __forceinline__ void angle_loads(ull addr, ull (*r)[4]) {
#pragma unroll
    for (int j = 0; j < K; j++) {
        LDG2(r[j][0], r[j][1], addr + S * 1024 * j);
        LDG2(r[j][2], r[j][3], addr + S * 1024 * j + 512);
    }
}
// adds for one angle: pixel p uses row {0,P1,P2,P3}[p]; 16 packed rn adds
template <int K, int P1, int P2, int P3>
__device__ __forceinline__ void angle_adds(ull (*r)[4], ull* acc) {
#pragma unroll
    for (int q = 0; q < 4; q++) acc[q]      = fadd2(acc[q],      r[0][q]);
#pragma unroll
    for (int q = 0; q < 4; q++) acc[4 + q]  = fadd2(acc[4 + q],  r[P1][q]);
#pragma unroll
    for (int q = 0; q < 4; q++) acc[8 + q]  = fadd2(acc[8 + q],  r[P2][q]);
#pragma unroll
    for (int q = 0; q < 4; q++) acc[12 + q] = fadd2(acc[12 + q], r[P3][q]);
}

// One pattern group, U angles per iteration: ALL U angle-loads issued
// before any add -> U*K*2 independent LDG.128 in flight.
template <int K, int S, int P1, int P2, int P3, int U>
__device__ __forceinline__ void run_group(int n, const unsigned* toff,
                                          int& idx, ull base, ull* acc) {
    int i = 0;
    for (; i + U <= n; i += U) {
        unsigned offs[U];
#pragma unroll
        for (int u = 0; u < U; u++) offs[u] = toff[idx + i + u];
        ull r[U][K][4];
#pragma unroll
        for (int u = 0; u < U; u++) angle_loads<K, S>(base + offs[u], r[u]);
#pragma unroll
        for (int u = 0; u < U; u++) angle_adds<K, P1, P2, P3>(r[u], acc);
    }
    for (; i < n; i++) {
        ull r[K][4];
        angle_loads<K, S>(base + toff[idx + i], r);
        angle_adds<K, P1, P2, P3>(r, acc);
    }
    idx += n;
}

// Main pass. CTA = 8 warps = 8 consecutive 4-px strips; warp = strip x 256 ch
// (lane = 16B channel slice, two 128-ch halves). Sorted table in SMEM.
template <int PASS>
__global__ __launch_bounds__(256, 3) void k_pass(float* __restrict__ outp) {
    __shared__ union SM {
        unsigned tw[8 * TS];         // 8 strip tables (3 KB)
        float stage[32 * 264];       // pass-A epilogue: 32 px x 256 ch (pad 8)
    } sm;

    const unsigned* tab = (PASS == 0) ? g_tabA : g_tabB;
    int tid = threadIdx.x;
    if (tid < 192)
        ((uint4*)sm.tw)[tid] =
            __ldg((const uint4*)(tab + (size_t)blockIdx.x * 8 * TS) + tid);
    __syncthreads();

    int w = tid >> 5, l = tid & 31;
    int s = blockIdx.x * 8 + w;
    int line = s >> 6, q0 = (s & 63) << 2;

    const unsigned* tw = sm.tw + w * TS;
    const unsigned char* cb = (const unsigned char*)tw;   // 16 cumulative counts
    const unsigned* toff = tw + 4;

    ull base;
    {
        const char* gp = (const char*)g_accT + l * 16;
        asm("cvta.to.global.u64 %0, %1;" : "=l"(base) : "l"(gp));
    }

    // acc[4p+0..1] = half0 (ch 4l..), acc[4p+2..3] = half1 (ch 128+4l..)
    ull acc[16];
#pragma unroll
    for (int i = 0; i < 16; i++) acc[i] = 0ull;

    int idx = 0;
#define GC(c) ((int)cb[c] - ((c) ? (int)cb[(c)-1] : 0))
    run_group<1,  1, 0, 0, 0, 4>(GC(0),  toff, idx, base, acc);
    run_group<2,  1, 1, 1, 1, 2>(GC(1),  toff, idx, base, acc);
    run_group<2,  1, 0, 1, 1, 2>(GC(2),  toff, idx, base, acc);
    run_group<3,  1, 1, 2, 2, 1>(GC(3),  toff, idx, base, acc);
    run_group<2,  1, 0, 0, 1, 2>(GC(4),  toff, idx, base, acc);
    run_group<3,  1, 1, 1, 2, 1>(GC(5),  toff, idx, base, acc);
    run_group<3,  1, 0, 1, 2, 1>(GC(6),  toff, idx, base, acc);
    run_group<4,  1, 1, 2, 3, 1>(GC(7),  toff, idx, base, acc);
    // code 8 impossible (flat+neg)
    run_group<2, -1, 1, 1, 1, 2>(GC(9),  toff, idx, base, acc);
    run_group<2, -1, 0, 1, 1, 2>(GC(10), toff, idx, base, acc);
    run_group<3, -1, 1, 2, 2, 1>(GC(11), toff, idx, base, acc);
    run_group<2, -1, 0, 0, 1, 2>(GC(12), toff, idx, base, acc);
    run_group<3, -1, 1, 1, 2, 1>(GC(13), toff, idx, base, acc);
    run_group<3, -1, 0, 1, 2, 1>(GC(14), toff, idx, base, acc);
    run_group<4, -1, 1, 2, 3, 1>(GC(15), toff, idx, base, acc);
#undef GC

    if (PASS == 1) {
        // pixel-major staging: pix = x*256 + y = line*256 + q0 + p
#pragma unroll
        for (int p = 0; p < 4; p++) {
            ull* pw = g_pBT + ((size_t)line * 256 + q0 + p) * 128;
            *reinterpret_cast<ulonglong2*>(pw + l * 2) =
                make_ulonglong2(acc[4 * p], acc[4 * p + 1]);
            *reinterpret_cast<ulonglong2*>(pw + 64 + l * 2) =
                make_ulonglong2(acc[4 * p + 2], acc[4 * p + 3]);
        }
        return;
    }

    // PASS A: fold pass-B partials; pixel (x=q0+p, y=line) -> pix = x*256+y
#pragma unroll
    for (int p = 0; p < 4; p++) {
        const ull* pr = g_pBT + ((size_t)(q0 + p) * 256 + line) * 128;
        ulonglong2 b0 = __ldg(reinterpret_cast<const ulonglong2*>(pr + l * 2));
        ulonglong2 b1 = __ldg(reinterpret_cast<const ulonglong2*>(pr + 64 + l * 2));
        acc[4 * p]     = fadd2(acc[4 * p],     b0.x);
        acc[4 * p + 1] = fadd2(acc[4 * p + 1], b0.y);
        acc[4 * p + 2] = fadd2(acc[4 * p + 2], b1.x);
        acc[4 * p + 3] = fadd2(acc[4 * p + 3], b1.y);
    }

    // epilogue: stage [32 px][256 ch] in SMEM, re-read channel-major,
    // store 32 contiguous x per channel (full-line coalesced)
    __syncthreads();   // table reads done before overwriting the union
#pragma unroll
    for (int p = 0; p < 4; p++) {
        float* st = sm.stage + (size_t)(w * 4 + p) * 264;
        *reinterpret_cast<float4*>(st + l * 4) =
            make_float4(u64lo(acc[4 * p]),     u64hi(acc[4 * p]),
                        u64lo(acc[4 * p + 1]), u64hi(acc[4 * p + 1]));
        *reinterpret_cast<float4*>(st + 128 + l * 4) =
            make_float4(u64lo(acc[4 * p + 2]), u64hi(acc[4 * p + 2]),
                        u64lo(acc[4 * p + 3]), u64hi(acc[4 * p + 3]));
    }
    __syncthreads();

    // thread tid == channel nc; CTA covers x in [X0, X0+32) at row `line`
    int X0 = (blockIdx.x & 7) << 5;
    float* op = outp + (size_t)tid * HW + (line << 8) + X0;
#pragma unroll
    for (int k = 0; k < 8; k++) {
        float4 q = make_float4(sm.stage[(size_t)(4 * k + 0) * 264 + tid],
                               sm.stage[(size_t)(4 * k + 1) * 264 + tid],
                               sm.stage[(size_t)(4 * k + 2) * 264 + tid],
                               sm.stage[(size_t)(4 * k + 3) * 264 + tid]);
        *reinterpret_cast<float4*>(op + 4 * k) = q;
    }
}

extern "C" void kernel_launch(void* const* d_in, const int* in_sizes, int n_in,
                              void* d_out, int out_size) {
    const float* acc = (const float*)d_in[0];
    float* out = (float*)d_out;

    k_trig<<<1, 192>>>();
    k_transpose<<<dim3(AR / 32, NC / 32), dim3(32, 8)>>>(acc);
    k_tab<<<dim3(NS4 / 8, 2), 256>>>();       // both sorted tables, one launch
    k_pass<1><<<NS4 / 8, 256>>>(out);         // pass B -> g_pBT (pixel-major)
    k_pass<0><<<NS4 / 8, 256>>>(out);         // pass A: += pBT fold, -> out
}

// round 12
// speedup vs baseline: 1.0973x; 1.0973x over previous
#include <cuda_runtime.h>

// Inverse discrete Hough transform, round 12 = round 11 (pattern-sorted,
// multi-angle-unrolled group gather) with:
//  - half-channel warps (4 px x 128 ch): acc 16 regs -> ~52 regs total ->
//    4+ CTAs/SM (occ 50%+), attacking the latency wall that capped R11
//  - CTA tile = 2 lines x 8 px: adjacent lines gather nearly identical rho
//    rows -> L1 reuse up, L2 pressure (71% in R11) down
// Pass B: angles 0..44 & 135..179, strips along y -> pBT[x*256+y][nc]
// Pass A: angles 45..134, strips along x, += pBT fold, -> out.

#define NA 180
#define NR 400
#define NC 256
#define OH 256
#define OW 256
#define AR (NA * NR)      // 72000
#define HW (OH * OW)      // 65536
#define NS4 16384         // strips of 4 px per pass
#define TS 96             // u32 per strip table: 4 (cum counts) + 90 offs + pad

typedef unsigned long long ull;

__device__ float  g_accT[AR * NC];                 // 73.7 MB: [a*400+r][nc]
__device__ float2 g_trig[NA];
__device__ unsigned g_tabA[(size_t)NS4 * TS];      // sorted per-strip tables
__device__ unsigned g_tabB[(size_t)NS4 * TS];
__device__ ull    g_pBT[(size_t)HW * 128];         // pass-B partial [x*256+y][nc/2]

__device__ __forceinline__ ull fadd2(ull a, ull b) {
    ull r;
    asm("add.rn.f32x2 %0, %1, %2;" : "=l"(r) : "l"(a), "l"(b));
    return r;
}
__device__ __forceinline__ float u64lo(ull u) {
    float a, b; asm("mov.b64 {%0,%1}, %2;" : "=f"(a), "=f"(b) : "l"(u)); return a;
}
__device__ __forceinline__ float u64hi(ull u) {
    float a, b; asm("mov.b64 {%0,%1}, %2;" : "=f"(a), "=f"(b) : "l"(u)); return b;
}
#define LDG2(v0, v1, addr)                                             \
    asm("ld.global.nc.v2.u64 {%0,%1}, [%2];"                           \
        : "=l"(v0), "=l"(v1) : "l"(addr))

__global__ void k_trig() {
    int a = threadIdx.x;
    if (a < NA) {
        // f32 theta (rn multiply), then correctly-rounded f32 cos/sin via
        // double (immune to fast-math; matches the JAX reference bit-exactly).
        float t = __fmul_rn((float)a, (float)(3.14159265358979323846 / 180.0));
        double td = (double)t;
        g_trig[a] = make_float2((float)cos(td), (float)sin(td));
    }
}

// 32x32 tiled transpose of acc[256][72000] -> g_accT[72000][256]
__global__ void k_transpose(const float* __restrict__ in) {
    __shared__ float tile[32][33];
    int tx = threadIdx.x, ty = threadIdx.y;           // 32 x 8
    int ar = blockIdx.x * 32 + tx;
#pragma unroll
    for (int k = 0; k < 4; k++)
        tile[ty + k * 8][tx] = in[(size_t)(blockIdx.y * 32 + ty + k * 8) * AR + ar];
    __syncthreads();
    int nc2 = blockIdx.y * 32 + tx;
#pragma unroll
    for (int k = 0; k < 4; k++)
        g_accT[(size_t)(blockIdx.x * 32 + ty + k * 8) * NC + nc2] = tile[tx][ty + k * 8];
}

// Table builder (both passes; pass = blockIdx.y). One warp per strip:
// exact offsets, pattern code (0 flat; 1..7 asc; 9..15 desc), then the 90
// base offsets sorted by code + 16 cumulative u8 counts.
__global__ void k_tab() {
    int pass = blockIdx.y;               // 0 = A (x-strips), 1 = B (y-strips)
    int tid = threadIdx.x, w = tid >> 5, l = tid & 31;
    int s = blockIdx.x * 8 + w;
    unsigned* tabw = ((pass == 0) ? g_tabA : g_tabB) + (size_t)s * TS;
    int line = s >> 6, q0 = (s & 63) << 2;

    unsigned codev[3], basev[3];
#pragma unroll
    for (int i = 0; i < 3; i++) {
        int ar = i * 32 + l;
        codev[i] = 0xFFFFu;
        if (ar < 90) {
            int a = (pass == 0) ? (45 + ar) : (ar < 45 ? ar : ar + 90);
            float2 cs = g_trig[a];
            unsigned off[4];
#pragma unroll
            for (int p = 0; p < 4; p++) {
                int x = (pass == 0) ? (q0 + p) : line;
                int y = (pass == 0) ? line : (q0 + p);
                // exact reference arithmetic: rn(rn(xc*c)+rn(yc*s)), rne round
                float sum = __fadd_rn(__fmul_rn((float)(x - 128), cs.x),
                                      __fmul_rn((float)(y - 128), cs.y));
                off[p] = (unsigned)(a * NR + __float2int_rn(sum) + 200) << 10;
            }
            int d1 = ((int)(off[1] - off[0])) >> 10;
            int d2 = ((int)(off[2] - off[0])) >> 10;
            int d3 = ((int)(off[3] - off[0])) >> 10;
            int b1 = d1 != 0, b2 = d2 != d1, b3 = d3 != d2;
            int bits = b1 | (b2 << 1) | (b3 << 2);
            int neg = (d1 < 0) | (d2 < 0) | (d3 < 0);
            codev[i] = (bits == 0) ? 0u : (unsigned)(bits + (neg ? 8 : 0));
            basev[i] = off[0];
        }
    }

    unsigned lmlt = (1u << l) - 1u;
    int cnt = 0;
    unsigned cword[4] = {0, 0, 0, 0};
#pragma unroll
    for (int c = 0; c < 16; c++) {
#pragma unroll
        for (int i = 0; i < 3; i++) {
            bool v = (codev[i] == (unsigned)c);
            unsigned m = __ballot_sync(0xFFFFFFFFu, v);
            if (v) tabw[4 + cnt + __popc(m & lmlt)] = basev[i];
            cnt += __popc(m);
        }
        cword[c >> 2] |= (unsigned)cnt << ((c & 3) * 8);
    }
    if (l == 0) {
        tabw[0] = cword[0]; tabw[1] = cword[1];
        tabw[2] = cword[2]; tabw[3] = cword[3];
    }
}

// loads for one angle (half-channel): K rows, 1 LDG.128-pair (16B/lane) each
template <int K, int S>
__device__ __forceinline__ void angle_loads(ull addr, ull (*r)[2]) {
#pragma unroll
    for (int j = 0; j < K; j++)
        LDG2(r[j][0], r[j][1], addr + S * 1024 * j);
}
// adds for one angle: pixel p uses row {0,P1,P2,P3}[p]; 8 packed rn adds
template <int K, int P1, int P2, int P3>
__device__ __forceinline__ void angle_adds(ull (*r)[2], ull* acc) {
    acc[0] = fadd2(acc[0], r[0][0]);  acc[1] = fadd2(acc[1], r[0][1]);
    acc[2] = fadd2(acc[2], r[P1][0]); acc[3] = fadd2(acc[3], r[P1][1]);
    acc[4] = fadd2(acc[4], r[P2][0]); acc[5] = fadd2(acc[5], r[P2][1]);
    acc[6] = fadd2(acc[6], r[P3][0]); acc[7] = fadd2(acc[7], r[P3][1]);
}

// One pattern group, U angles per iteration: all U angle-loads issued
// before any dependent add -> U*K independent LDG.128 in flight.
template <int K, int S, int P1, int P2, int P3, int U>
__device__ __forceinline__ void run_group(int n, const unsigned* toff,
                                          int& idx, ull base, ull* acc) {
    int i = 0;
    for (; i + U <= n; i += U) {
        unsigned offs[U];
#pragma unroll
        for (int u = 0; u < U; u++) offs[u] = toff[idx + i + u];
        ull r[U][K][2];
#pragma unroll
        for (int u = 0; u < U; u++) angle_loads<K, S>(base + offs[u], r[u]);
#pragma unroll
        for (int u = 0; u < U; u++) angle_adds<K, P1, P2, P3>(r[u], acc);
    }
    for (; i < n; i++) {
        ull r[K][2];
        angle_loads<K, S>(base + toff[idx + i], r);
        angle_adds<K, P1, P2, P3>(r, acc);
    }
    idx += n;
}

// Main pass. CTA = 8 warps = 4 strips (2 lines x 2 positions) x 2 channel
// halves; warp = 4 px x 128 ch (lane = 16B slice). Sorted tables in SMEM.
template <int PASS>
__global__ __launch_bounds__(256, 4) void k_pass(float* __restrict__ outp) {
    __shared__ union SM {
        unsigned tw[4 * TS];         // 4 strip tables (1.5 KB)
        float stage[16 * 264];       // pass-A epilogue: 16 px x 256 ch (pad 8)
    } sm;

    const unsigned* tab = (PASS == 0) ? g_tabA : g_tabB;
    int tid = threadIdx.x, w = tid >> 5, l = tid & 31;
    int half = w & 1, t = w >> 1;              // strip-local 0..3
    int jj = blockIdx.x >> 5, kk = blockIdx.x & 31;
    int dl = t & 1, dq = t >> 1;
    int line = 2 * jj + dl;
    int pos = 2 * kk + dq;                     // strip position within line
    int q0 = pos << 2;
    int s = line * 64 + pos;

    if (half == 0 && l < 24)
        ((uint4*)(sm.tw + t * TS))[l] =
            __ldg((const uint4*)(tab + (size_t)s * TS) + l);
    __syncthreads();

    const unsigned* tw = sm.tw + t * TS;
    const unsigned char* cb = (const unsigned char*)tw;   // cumulative counts
    const unsigned* toff = tw + 4;

    ull base;
    {
        const char* gp = (const char*)g_accT + half * 512 + l * 16;
        asm("cvta.to.global.u64 %0, %1;" : "=l"(base) : "l"(gp));
    }

    // acc[2p+q]: pixel p, channels half*128 + l*4 + 2q .. +2q+1
    ull acc[8];
#pragma unroll
    for (int i = 0; i < 8; i++) acc[i] = 0ull;

    int idx = 0;
#define GC(c) ((int)cb[c] - ((c) ? (int)cb[(c)-1] : 0))
    run_group<1,  1, 0, 0, 0, 4>(GC(0),  toff, idx, base, acc);
    run_group<2,  1, 1, 1, 1, 2>(GC(1),  toff, idx, base, acc);
    run_group<2,  1, 0, 1, 1, 2>(GC(2),  toff, idx, base, acc);
    run_group<3,  1, 1, 2, 2, 2>(GC(3),  toff, idx, base, acc);
    run_group<2,  1, 0, 0, 1, 2>(GC(4),  toff, idx, base, acc);
    run_group<3,  1, 1, 1, 2, 2>(GC(5),  toff, idx, base, acc);
    run_group<3,  1, 0, 1, 2, 2>(GC(6),  toff, idx, base, acc);
    run_group<4,  1, 1, 2, 3, 1>(GC(7),  toff, idx, base, acc);
    // code 8 impossible (flat+neg)
    run_group<2, -1, 1, 1, 1, 2>(GC(9),  toff, idx, base, acc);
    run_group<2, -1, 0, 1, 1, 2>(GC(10), toff, idx, base, acc);
    run_group<3, -1, 1, 2, 2, 2>(GC(11), toff, idx, base, acc);
    run_group<2, -1, 0, 0, 1, 2>(GC(12), toff, idx, base, acc);
    run_group<3, -1, 1, 1, 2, 2>(GC(13), toff, idx, base, acc);
    run_group<3, -1, 0, 1, 2, 2>(GC(14), toff, idx, base, acc);
    run_group<4, -1, 1, 2, 3, 1>(GC(15), toff, idx, base, acc);
#undef GC

    if (PASS == 1) {
        // pixel-major staging: pix = x*256 + y = line*256 + q0 + p
#pragma unroll
        for (int p = 0; p < 4; p++) {
            ull* pw = g_pBT + ((size_t)line * 256 + q0 + p) * 128 + half * 64;
            *reinterpret_cast<ulonglong2*>(pw + l * 2) =
                make_ulonglong2(acc[2 * p], acc[2 * p + 1]);
        }
        return;
    }

    // PASS A: fold pass-B partials; pixel (x=q0+p, y=line) -> pix = x*256+y
#pragma unroll
    for (int p = 0; p < 4; p++) {
        const ull* pr = g_pBT + ((size_t)(q0 + p) * 256 + line) * 128 + half * 64;
        ulonglong2 b = __ldg(reinterpret_cast<const ulonglong2*>(pr + l * 2));
        acc[2 * p]     = fadd2(acc[2 * p],     b.x);
        acc[2 * p + 1] = fadd2(acc[2 * p + 1], b.y);
    }

    // epilogue: stage [16 px][256 ch] in SMEM (px_local = dl*8 + dq*4 + p),
    // re-read channel-major, store 8 contiguous x per line per channel
    __syncthreads();   // table reads done before overwriting the union
#pragma unroll
    for (int p = 0; p < 4; p++) {
        float* st = sm.stage + (size_t)(dl * 8 + dq * 4 + p) * 264
                  + half * 128 + l * 4;
        *reinterpret_cast<float4*>(st) =
            make_float4(u64lo(acc[2 * p]),     u64hi(acc[2 * p]),
                        u64lo(acc[2 * p + 1]), u64hi(acc[2 * p + 1]));
    }
    __syncthreads();

    // thread tid == channel nc; CTA covers lines {2jj, 2jj+1}, x in [8kk, 8kk+8)
#pragma unroll
    for (int dl2 = 0; dl2 < 2; dl2++) {
        float* op = outp + (size_t)tid * HW + (2 * jj + dl2) * 256 + 8 * kk;
#pragma unroll
        for (int g = 0; g < 2; g++) {
            float4 q = make_float4(
                sm.stage[(size_t)(dl2 * 8 + 4 * g + 0) * 264 + tid],
                sm.stage[(size_t)(dl2 * 8 + 4 * g + 1) * 264 + tid],
                sm.stage[(size_t)(dl2 * 8 + 4 * g + 2) * 264 + tid],
                sm.stage[(size_t)(dl2 * 8 + 4 * g + 3) * 264 + tid]);
            *reinterpret_cast<float4*>(op + 4 * g) = q;
        }
    }
}

extern "C" void kernel_launch(void* const* d_in, const int* in_sizes, int n_in,
                              void* d_out, int out_size) {
    const float* acc = (const float*)d_in[0];
    float* out = (float*)d_out;

    k_trig<<<1, 192>>>();
    k_transpose<<<dim3(AR / 32, NC / 32), dim3(32, 8)>>>(acc);
    k_tab<<<dim3(NS4 / 8, 2), 256>>>();       // both sorted tables, one launch
    k_pass<1><<<4096, 256>>>(out);            // pass B -> g_pBT (pixel-major)
    k_pass<0><<<4096, 256>>>(out);            // pass A: += pBT fold, -> out
}

// round 13
// speedup vs baseline: 1.1273x; 1.0273x over previous
#include <cuda_runtime.h>

// Inverse discrete Hough transform, round 13 = round 12 with a 4-line x 8-px
// CTA tile (512 threads, 16 warps = 8 strips x 2 channel halves, 2 CTAs/SM).
// L2 was the binding pipe in R12 (75.6%); rows fetched per angle per tile
// scale as (1+(W-1)g)+(L-1), so 4x8 cuts L2 bytes/pixel 0.29 -> 0.21 (x0.71).
// Gather loop, sorted tables, k_tab, fold and staging logic unchanged.
// Pass B: angles 0..44 & 135..179, strips along y -> pBT[x*256+y][nc]
// Pass A: angles 45..134, strips along x, += pBT fold, -> out.

#define NA 180
#define NR 400
#define NC 256
#define OH 256
#define OW 256
#define AR (NA * NR)      // 72000
#define HW (OH * OW)      // 65536
#define NS4 16384         // strips of 4 px per pass
#define TS 96             // u32 per strip table: 4 (cum counts) + 90 offs + pad

typedef unsigned long long ull;

__device__ float  g_accT[AR * NC];                 // 73.7 MB: [a*400+r][nc]
__device__ float2 g_trig[NA];
__device__ unsigned g_tabA[(size_t)NS4 * TS];      // sorted per-strip tables
__device__ unsigned g_tabB[(size_t)NS4 * TS];
__device__ ull    g_pBT[(size_t)HW * 128];         // pass-B partial [x*256+y][nc/2]

__device__ __forceinline__ ull fadd2(ull a, ull b) {
    ull r;
    asm("add.rn.f32x2 %0, %1, %2;" : "=l"(r) : "l"(a), "l"(b));
    return r;
}
__device__ __forceinline__ float u64lo(ull u) {
    float a, b; asm("mov.b64 {%0,%1}, %2;" : "=f"(a), "=f"(b) : "l"(u)); return a;
}
__device__ __forceinline__ float u64hi(ull u) {
    float a, b; asm("mov.b64 {%0,%1}, %2;" : "=f"(a), "=f"(b) : "l"(u)); return b;
}
#define LDG2(v0, v1, addr)                                             \
    asm("ld.global.nc.v2.u64 {%0,%1}, [%2];"                           \
        : "=l"(v0), "=l"(v1) : "l"(addr))

__global__ void k_trig() {
    int a = threadIdx.x;
    if (a < NA) {
        // f32 theta (rn multiply), then correctly-rounded f32 cos/sin via
        // double (immune to fast-math; matches the JAX reference bit-exactly).
        float t = __fmul_rn((float)a, (float)(3.14159265358979323846 / 180.0));
        double td = (double)t;
        g_trig[a] = make_float2((float)cos(td), (float)sin(td));
    }
}

// 32x32 tiled transpose of acc[256][72000] -> g_accT[72000][256]
__global__ void k_transpose(const float* __restrict__ in) {
    __shared__ float tile[32][33];
    int tx = threadIdx.x, ty = threadIdx.y;           // 32 x 8
    int ar = blockIdx.x * 32 + tx;
#pragma unroll
    for (int k = 0; k < 4; k++)
        tile[ty + k * 8][tx] = in[(size_t)(blockIdx.y * 32 + ty + k * 8) * AR + ar];
    __syncthreads();
    int nc2 = blockIdx.y * 32 + tx;
#pragma unroll
    for (int k = 0; k < 4; k++)
        g_accT[(size_t)(blockIdx.x * 32 + ty + k * 8) * NC + nc2] = tile[tx][ty + k * 8];
}

// Table builder (both passes; pass = blockIdx.y). One warp per strip:
// exact offsets, pattern code (0 flat; 1..7 asc; 9..15 desc), then the 90
// base offsets sorted by code + 16 cumulative u8 counts.
__global__ void k_tab() {
    int pass = blockIdx.y;               // 0 = A (x-strips), 1 = B (y-strips)
    int tid = threadIdx.x, w = tid >> 5, l = tid & 31;
    int s = blockIdx.x * 8 + w;
    unsigned* tabw = ((pass == 0) ? g_tabA : g_tabB) + (size_t)s * TS;
    int line = s >> 6, q0 = (s & 63) << 2;

    unsigned codev[3], basev[3];
#pragma unroll
    for (int i = 0; i < 3; i++) {
        int ar = i * 32 + l;
        codev[i] = 0xFFFFu;
        if (ar < 90) {
            int a = (pass == 0) ? (45 + ar) : (ar < 45 ? ar : ar + 90);
            float2 cs = g_trig[a];
            unsigned off[4];
#pragma unroll
            for (int p = 0; p < 4; p++) {
                int x = (pass == 0) ? (q0 + p) : line;
                int y = (pass == 0) ? line : (q0 + p);
                // exact reference arithmetic: rn(rn(xc*c)+rn(yc*s)), rne round
                float sum = __fadd_rn(__fmul_rn((float)(x - 128), cs.x),
                                      __fmul_rn((float)(y - 128), cs.y));
                off[p] = (unsigned)(a * NR + __float2int_rn(sum) + 200) << 10;
            }
            int d1 = ((int)(off[1] - off[0])) >> 10;
            int d2 = ((int)(off[2] - off[0])) >> 10;
            int d3 = ((int)(off[3] - off[0])) >> 10;
            int b1 = d1 != 0, b2 = d2 != d1, b3 = d3 != d2;
            int bits = b1 | (b2 << 1) | (b3 << 2);
            int neg = (d1 < 0) | (d2 < 0) | (d3 < 0);
            codev[i] = (bits == 0) ? 0u : (unsigned)(bits + (neg ? 8 : 0));
            basev[i] = off[0];
        }
    }

    unsigned lmlt = (1u << l) - 1u;
    int cnt = 0;
    unsigned cword[4] = {0, 0, 0, 0};
#pragma unroll
    for (int c = 0; c < 16; c++) {
#pragma unroll
        for (int i = 0; i < 3; i++) {
            bool v = (codev[i] == (unsigned)c);
            unsigned m = __ballot_sync(0xFFFFFFFFu, v);
            if (v) tabw[4 + cnt + __popc(m & lmlt)] = basev[i];
            cnt += __popc(m);
        }
        cword[c >> 2] |= (unsigned)cnt << ((c & 3) * 8);
    }
    if (l == 0) {
        tabw[0] = cword[0]; tabw[1] = cword[1];
        tabw[2] = cword[2]; tabw[3] = cword[3];
    }
}

// loads for one angle (half-channel): K rows, 1 LDG.128-pair (16B/lane) each
template <int K, int S>
__device__ __forceinline__ void angle_loads(ull addr, ull (*r)[2]) {
#pragma unroll
    for (int j = 0; j < K; j++)
        LDG2(r[j][0], r[j][1], addr + S * 1024 * j);
}
// adds for one angle: pixel p uses row {0,P1,P2,P3}[p]; 8 packed rn adds
template <int K, int P1, int P2, int P3>
__device__ __forceinline__ void angle_adds(ull (*r)[2], ull* acc) {
    acc[0] = fadd2(acc[0], r[0][0]);  acc[1] = fadd2(acc[1], r[0][1]);
    acc[2] = fadd2(acc[2], r[P1][0]); acc[3] = fadd2(acc[3], r[P1][1]);
    acc[4] = fadd2(acc[4], r[P2][0]); acc[5] = fadd2(acc[5], r[P2][1]);
    acc[6] = fadd2(acc[6], r[P3][0]); acc[7] = fadd2(acc[7], r[P3][1]);
}

// One pattern group, U angles per iteration: all U angle-loads issued
// before any dependent add -> U*K independent LDG.128 in flight.
template <int K, int S, int P1, int P2, int P3, int U>
__device__ __forceinline__ void run_group(int n, const unsigned* toff,
                                          int& idx, ull base, ull* acc) {
    int i = 0;
    for (; i + U <= n; i += U) {
        unsigned offs[U];
#pragma unroll
        for (int u = 0; u < U; u++) offs[u] = toff[idx + i + u];
        ull r[U][K][2];
#pragma unroll
        for (int u = 0; u < U; u++) angle_loads<K, S>(base + offs[u], r[u]);
#pragma unroll
        for (int u = 0; u < U; u++) angle_adds<K, P1, P2, P3>(r[u], acc);
    }
    for (; i < n; i++) {
        ull r[K][2];
        angle_loads<K, S>(base + toff[idx + i], r);
        angle_adds<K, P1, P2, P3>(r, acc);
    }
    idx += n;
}

// Main pass. CTA = 512 threads = 16 warps = 8 strips (4 lines x 2 positions)
// x 2 channel halves; warp = 4 px x 128 ch (lane = 16B slice).
template <int PASS>
__global__ __launch_bounds__(512, 2) void k_pass(float* __restrict__ outp) {
    __shared__ union SM {
        unsigned tw[8 * TS];         // 8 strip tables (3 KB)
        float stage[32 * 264];       // pass-A epilogue: 32 px x 256 ch (pad 8)
    } sm;

    const unsigned* tab = (PASS == 0) ? g_tabA : g_tabB;
    int tid = threadIdx.x, w = tid >> 5, l = tid & 31;
    int half = w & 1, t = w >> 1;              // strip-local 0..7
    int dl = t & 3, dq = t >> 2;
    int jj = blockIdx.x >> 5, kk = blockIdx.x & 31;
    int line = 4 * jj + dl;
    int pos = 2 * kk + dq;
    int q0 = pos << 2;
    int s = line * 64 + pos;

    if (half == 0 && l < 24)
        ((uint4*)(sm.tw + t * TS))[l] =
            __ldg((const uint4*)(tab + (size_t)s * TS) + l);
    __syncthreads();

    const unsigned* tw = sm.tw + t * TS;
    const unsigned char* cb = (const unsigned char*)tw;   // cumulative counts
    const unsigned* toff = tw + 4;

    ull base;
    {
        const char* gp = (const char*)g_accT + half * 512 + l * 16;
        asm("cvta.to.global.u64 %0, %1;" : "=l"(base) : "l"(gp));
    }

    // acc[2p+q]: pixel p, channels half*128 + l*4 + 2q .. +2q+1
    ull acc[8];
#pragma unroll
    for (int i = 0; i < 8; i++) acc[i] = 0ull;

    int idx = 0;
#define GC(c) ((int)cb[c] - ((c) ? (int)cb[(c)-1] : 0))
    run_group<1,  1, 0, 0, 0, 4>(GC(0),  toff, idx, base, acc);
    run_group<2,  1, 1, 1, 1, 2>(GC(1),  toff, idx, base, acc);
    run_group<2,  1, 0, 1, 1, 2>(GC(2),  toff, idx, base, acc);
    run_group<3,  1, 1, 2, 2, 2>(GC(3),  toff, idx, base, acc);
    run_group<2,  1, 0, 0, 1, 2>(GC(4),  toff, idx, base, acc);
    run_group<3,  1, 1, 1, 2, 2>(GC(5),  toff, idx, base, acc);
    run_group<3,  1, 0, 1, 2, 2>(GC(6),  toff, idx, base, acc);
    run_group<4,  1, 1, 2, 3, 1>(GC(7),  toff, idx, base, acc);
    // code 8 impossible (flat+neg)
    run_group<2, -1, 1, 1, 1, 2>(GC(9),  toff, idx, base, acc);
    run_group<2, -1, 0, 1, 1, 2>(GC(10), toff, idx, base, acc);
    run_group<3, -1, 1, 2, 2, 2>(GC(11), toff, idx, base, acc);
    run_group<2, -1, 0, 0, 1, 2>(GC(12), toff, idx, base, acc);
    run_group<3, -1, 1, 1, 2, 2>(GC(13), toff, idx, base, acc);
    run_group<3, -1, 0, 1, 2, 2>(GC(14), toff, idx, base, acc);
    run_group<4, -1, 1, 2, 3, 1>(GC(15), toff, idx, base, acc);
#undef GC

    if (PASS == 1) {
        // pixel-major staging: pix = x*256 + y = line*256 + q0 + p
#pragma unroll
        for (int p = 0; p < 4; p++) {
            ull* pw = g_pBT + ((size_t)line * 256 + q0 + p) * 128 + half * 64;
            *reinterpret_cast<ulonglong2*>(pw + l * 2) =
                make_ulonglong2(acc[2 * p], acc[2 * p + 1]);
        }
        return;
    }

    // PASS A: fold pass-B partials; pixel (x=q0+p, y=line) -> pix = x*256+y
#pragma unroll
    for (int p = 0; p < 4; p++) {
        const ull* pr = g_pBT + ((size_t)(q0 + p) * 256 + line) * 128 + half * 64;
        ulonglong2 b = __ldg(reinterpret_cast<const ulonglong2*>(pr + l * 2));
        acc[2 * p]     = fadd2(acc[2 * p],     b.x);
        acc[2 * p + 1] = fadd2(acc[2 * p + 1], b.y);
    }

    // epilogue: stage [32 px][256 ch] in SMEM (px_local = dl*8 + dq*4 + p),
    // re-read channel-major, store 8 contiguous x per line per channel
    __syncthreads();   // table reads done before overwriting the union
#pragma unroll
    for (int p = 0; p < 4; p++) {
        float* st = sm.stage + (size_t)(dl * 8 + dq * 4 + p) * 264
                  + half * 128 + l * 4;
        *reinterpret_cast<float4*>(st) =
            make_float4(u64lo(acc[2 * p]),     u64hi(acc[2 * p]),
                        u64lo(acc[2 * p + 1]), u64hi(acc[2 * p + 1]));
    }
    __syncthreads();

    // final store: thread half t2 handles lines {2t2, 2t2+1} of the 4-line
    // tile; c = channel. CTA covers x in [8kk, 8kk+8).
    {
        int t2 = tid >> 8, c = tid & 255;
#pragma unroll
        for (int dl2 = 0; dl2 < 2; dl2++) {
            int DL = 2 * t2 + dl2;
            float* op = outp + (size_t)c * HW + (4 * jj + DL) * 256 + 8 * kk;
#pragma unroll
            for (int g = 0; g < 2; g++) {
                float4 q = make_float4(
                    sm.stage[(size_t)(DL * 8 + 4 * g + 0) * 264 + c],
                    sm.stage[(size_t)(DL * 8 + 4 * g + 1) * 264 + c],
                    sm.stage[(size_t)(DL * 8 + 4 * g + 2) * 264 + c],
                    sm.stage[(size_t)(DL * 8 + 4 * g + 3) * 264 + c]);
                *reinterpret_cast<float4*>(op + 4 * g) = q;
            }
        }
    }
}

extern "C" void kernel_launch(void* const* d_in, const int* in_sizes, int n_in,
                              void* d_out, int out_size) {
    const float* acc = (const float*)d_in[0];
    float* out = (float*)d_out;

    k_trig<<<1, 192>>>();
    k_transpose<<<dim3(AR / 32, NC / 32), dim3(32, 8)>>>(acc);
    k_tab<<<dim3(NS4 / 8, 2), 256>>>();       // both sorted tables, one launch
    k_pass<1><<<2048, 512>>>(out);            // pass B -> g_pBT (pixel-major)
    k_pass<0><<<2048, 512>>>(out);            // pass A: += pBT fold, -> out
}

// round 14
// speedup vs baseline: 1.1485x; 1.0188x over previous
#include <cuda_runtime.h>

// Inverse discrete Hough transform, round 14 = round 13 with a 4-line x 16-px
// CTA tile (1024 threads, 32 warps = 16 strips x 2 channel halves, 1 CTA/SM).
// L1 (69%) and L2 (72%) are co-binding; rows/px drops 0.21 -> 0.15 so L2
// traffic falls x0.71, de-serializing the L1 floor. Warp-level gather,
// sorted tables, k_tab and fold are byte-identical to R13. The pass-A
// epilogue stages 64 px in two 32-px rounds (48KB static smem limit).
// Pass B: angles 0..44 & 135..179, strips along y -> pBT[x*256+y][nc]
// Pass A: angles 45..134, strips along x, += pBT fold, -> out.

#define NA 180
#define NR 400
#define NC 256
#define OH 256
#define OW 256
#define AR (NA * NR)      // 72000
#define HW (OH * OW)      // 65536
#define NS4 16384         // strips of 4 px per pass
#define TS 96             // u32 per strip table: 4 (cum counts) + 90 offs + pad

typedef unsigned long long ull;

__device__ float  g_accT[AR * NC];                 // 73.7 MB: [a*400+r][nc]
__device__ float2 g_trig[NA];
__device__ unsigned g_tabA[(size_t)NS4 * TS];      // sorted per-strip tables
__device__ unsigned g_tabB[(size_t)NS4 * TS];
__device__ ull    g_pBT[(size_t)HW * 128];         // pass-B partial [x*256+y][nc/2]

__device__ __forceinline__ ull fadd2(ull a, ull b) {
    ull r;
    asm("add.rn.f32x2 %0, %1, %2;" : "=l"(r) : "l"(a), "l"(b));
    return r;
}
__device__ __forceinline__ float u64lo(ull u) {
    float a, b; asm("mov.b64 {%0,%1}, %2;" : "=f"(a), "=f"(b) : "l"(u)); return a;
}
__device__ __forceinline__ float u64hi(ull u) {
    float a, b; asm("mov.b64 {%0,%1}, %2;" : "=f"(a), "=f"(b) : "l"(u)); return b;
}
#define LDG2(v0, v1, addr)                                             \
    asm("ld.global.nc.v2.u64 {%0,%1}, [%2];"                           \
        : "=l"(v0), "=l"(v1) : "l"(addr))

__global__ void k_trig() {
    int a = threadIdx.x;
    if (a < NA) {
        // f32 theta (rn multiply), then correctly-rounded f32 cos/sin via
        // double (immune to fast-math; matches the JAX reference bit-exactly).
        float t = __fmul_rn((float)a, (float)(3.14159265358979323846 / 180.0));
        double td = (double)t;
        g_trig[a] = make_float2((float)cos(td), (float)sin(td));
    }
}

// 32x32 tiled transpose of acc[256][72000] -> g_accT[72000][256]
__global__ void k_transpose(const float* __restrict__ in) {
    __shared__ float tile[32][33];
    int tx = threadIdx.x, ty = threadIdx.y;           // 32 x 8
    int ar = blockIdx.x * 32 + tx;
#pragma unroll
    for (int k = 0; k < 4; k++)
        tile[ty + k * 8][tx] = in[(size_t)(blockIdx.y * 32 + ty + k * 8) * AR + ar];
    __syncthreads();
    int nc2 = blockIdx.y * 32 + tx;
#pragma unroll
    for (int k = 0; k < 4; k++)
        g_accT[(size_t)(blockIdx.x * 32 + ty + k * 8) * NC + nc2] = tile[tx][ty + k * 8];
}

// Table builder (both passes; pass = blockIdx.y). One warp per strip:
// exact offsets, pattern code (0 flat; 1..7 asc; 9..15 desc), then the 90
// base offsets sorted by code + 16 cumulative u8 counts.
__global__ void k_tab() {
    int pass = blockIdx.y;               // 0 = A (x-strips), 1 = B (y-strips)
    int tid = threadIdx.x, w = tid >> 5, l = tid & 31;
    int s = blockIdx.x * 8 + w;
    unsigned* tabw = ((pass == 0) ? g_tabA : g_tabB) + (size_t)s * TS;
    int line = s >> 6, q0 = (s & 63) << 2;

    unsigned codev[3], basev[3];
#pragma unroll
    for (int i = 0; i < 3; i++) {
        int ar = i * 32 + l;
        codev[i] = 0xFFFFu;
        if (ar < 90) {
            int a = (pass == 0) ? (45 + ar) : (ar < 45 ? ar : ar + 90);
            float2 cs = g_trig[a];
            unsigned off[4];
#pragma unroll
            for (int p = 0; p < 4; p++) {
                int x = (pass == 0) ? (q0 + p) : line;
                int y = (pass == 0) ? line : (q0 + p);
                // exact reference arithmetic: rn(rn(xc*c)+rn(yc*s)), rne round
                float sum = __fadd_rn(__fmul_rn((float)(x - 128), cs.x),
                                      __fmul_rn((float)(y - 128), cs.y));
                off[p] = (unsigned)(a * NR + __float2int_rn(sum) + 200) << 10;
            }
            int d1 = ((int)(off[1] - off[0])) >> 10;
            int d2 = ((int)(off[2] - off[0])) >> 10;
            int d3 = ((int)(off[3] - off[0])) >> 10;
            int b1 = d1 != 0, b2 = d2 != d1, b3 = d3 != d2;
            int bits = b1 | (b2 << 1) | (b3 << 2);
            int neg = (d1 < 0) | (d2 < 0) | (d3 < 0);
            codev[i] = (bits == 0) ? 0u : (unsigned)(bits + (neg ? 8 : 0));
            basev[i] = off[0];
        }
    }

    unsigned lmlt = (1u << l) - 1u;
    int cnt = 0;
    unsigned cword[4] = {0, 0, 0, 0};
#pragma unroll
    for (int c = 0; c < 16; c++) {
#pragma unroll
        for (int i = 0; i < 3; i++) {
            bool v = (codev[i] == (unsigned)c);
            unsigned m = __ballot_sync(0xFFFFFFFFu, v);
            if (v) tabw[4 + cnt + __popc(m & lmlt)] = basev[i];
            cnt += __popc(m);
        }
        cword[c >> 2] |= (unsigned)cnt << ((c & 3) * 8);
    }
    if (l == 0) {
        tabw[0] = cword[0]; tabw[1] = cword[1];
        tabw[2] = cword[2]; tabw[3] = cword[3];
    }
}

// loads for one angle (half-channel): K rows, 1 LDG.128-pair (16B/lane) each
template <int K, int S>
__device__ __forceinline__ void angle_loads(ull addr, ull (*r)[2]) {
#pragma unroll
    for (int j = 0; j < K; j++)
        LDG2(r[j][0], r[j][1], addr + S * 1024 * j);
}
// adds for one angle: pixel p uses row {0,P1,P2,P3}[p]; 8 packed rn adds
template <int K, int P1, int P2, int P3>
__device__ __forceinline__ void angle_adds(ull (*r)[2], ull* acc) {
    acc[0] = fadd2(acc[0], r[0][0]);  acc[1] = fadd2(acc[1], r[0][1]);
    acc[2] = fadd2(acc[2], r[P1][0]); acc[3] = fadd2(acc[3], r[P1][1]);
    acc[4] = fadd2(acc[4], r[P2][0]); acc[5] = fadd2(acc[5], r[P2][1]);
    acc[6] = fadd2(acc[6], r[P3][0]); acc[7] = fadd2(acc[7], r[P3][1]);
}

// One pattern group, U angles per iteration: all U angle-loads issued
// before any dependent add -> U*K independent LDG.128 in flight.
template <int K, int S, int P1, int P2, int P3, int U>
__device__ __forceinline__ void run_group(int n, const unsigned* toff,
                                          int& idx, ull base, ull* acc) {
    int i = 0;
    for (; i + U <= n; i += U) {
        unsigned offs[U];
#pragma unroll
        for (int u = 0; u < U; u++) offs[u] = toff[idx + i + u];
        ull r[U][K][2];
#pragma unroll
        for (int u = 0; u < U; u++) angle_loads<K, S>(base + offs[u], r[u]);
#pragma unroll
        for (int u = 0; u < U; u++) angle_adds<K, P1, P2, P3>(r[u], acc);
    }
    for (; i < n; i++) {
        ull r[K][2];
        angle_loads<K, S>(base + toff[idx + i], r);
        angle_adds<K, P1, P2, P3>(r, acc);
    }
    idx += n;
}

// Main pass. CTA = 1024 threads = 32 warps = 16 strips (4 lines x 4 positions)
// x 2 channel halves; warp = 4 px x 128 ch (lane = 16B slice).
template <int PASS>
__global__ __launch_bounds__(1024, 1) void k_pass(float* __restrict__ outp) {
    __shared__ union SM {
        unsigned tw[16 * TS];        // 16 strip tables (6 KB)
        float stage[32 * 264];       // epilogue: 32 px x 256 ch (two rounds)
    } sm;

    const unsigned* tab = (PASS == 0) ? g_tabA : g_tabB;
    int tid = threadIdx.x, w = tid >> 5, l = tid & 31;
    int half = w & 1, t = w >> 1;              // strip-local 0..15
    int dl = t & 3, dq = t >> 2;               // line 0..3, position 0..3
    int jj = blockIdx.x >> 4, kk = blockIdx.x & 15;
    int line = 4 * jj + dl;
    int pos = 4 * kk + dq;
    int q0 = pos << 2;
    int s = line * 64 + pos;

    if (half == 0 && l < 24)
        ((uint4*)(sm.tw + t * TS))[l] =
            __ldg((const uint4*)(tab + (size_t)s * TS) + l);
    __syncthreads();

    const unsigned* tw = sm.tw + t * TS;
    const unsigned char* cb = (const unsigned char*)tw;   // cumulative counts
    const unsigned* toff = tw + 4;

    ull base;
    {
        const char* gp = (const char*)g_accT + half * 512 + l * 16;
        asm("cvta.to.global.u64 %0, %1;" : "=l"(base) : "l"(gp));
    }

    // acc[2p+q]: pixel p, channels half*128 + l*4 + 2q .. +2q+1
    ull acc[8];
#pragma unroll
    for (int i = 0; i < 8; i++) acc[i] = 0ull;

    int idx = 0;
#define GC(c) ((int)cb[c] - ((c) ? (int)cb[(c)-1] : 0))
    run_group<1,  1, 0, 0, 0, 4>(GC(0),  toff, idx, base, acc);
    run_group<2,  1, 1, 1, 1, 2>(GC(1),  toff, idx, base, acc);
    run_group<2,  1, 0, 1, 1, 2>(GC(2),  toff, idx, base, acc);
    run_group<3,  1, 1, 2, 2, 2>(GC(3),  toff, idx, base, acc);
    run_group<2,  1, 0, 0, 1, 2>(GC(4),  toff, idx, base, acc);
    run_group<3,  1, 1, 1, 2, 2>(GC(5),  toff, idx, base, acc);
    run_group<3,  1, 0, 1, 2, 2>(GC(6),  toff, idx, base, acc);
    run_group<4,  1, 1, 2, 3, 1>(GC(7),  toff, idx, base, acc);
    // code 8 impossible (flat+neg)
    run_group<2, -1, 1, 1, 1, 2>(GC(9),  toff, idx, base, acc);
    run_group<2, -1, 0, 1, 1, 2>(GC(10), toff, idx, base, acc);
    run_group<3, -1, 1, 2, 2, 2>(GC(11), toff, idx, base, acc);
    run_group<2, -1, 0, 0, 1, 2>(GC(12), toff, idx, base, acc);
    run_group<3, -1, 1, 1, 2, 2>(GC(13), toff, idx, base, acc);
    run_group<3, -1, 0, 1, 2, 2>(GC(14), toff, idx, base, acc);
    run_group<4, -1, 1, 2, 3, 1>(GC(15), toff, idx, base, acc);
#undef GC

    if (PASS == 1) {
        // pixel-major staging: pix = x*256 + y = line*256 + q0 + p
#pragma unroll
        for (int p = 0; p < 4; p++) {
            ull* pw = g_pBT + ((size_t)line * 256 + q0 + p) * 128 + half * 64;
            *reinterpret_cast<ulonglong2*>(pw + l * 2) =
                make_ulonglong2(acc[2 * p], acc[2 * p + 1]);
        }
        return;
    }

    // PASS A: fold pass-B partials; pixel (x=q0+p, y=line) -> pix = x*256+y
#pragma unroll
    for (int p = 0; p < 4; p++) {
        const ull* pr = g_pBT + ((size_t)(q0 + p) * 256 + line) * 128 + half * 64;
        ulonglong2 b = __ldg(reinterpret_cast<const ulonglong2*>(pr + l * 2));
        acc[2 * p]     = fadd2(acc[2 * p],     b.x);
        acc[2 * p + 1] = fadd2(acc[2 * p + 1], b.y);
    }

    // epilogue in two rounds of 2 lines (32 px) each; stage [32 px][256 ch],
    // re-read channel-major, store 16 contiguous x per line per channel
    int c = tid & 255, u = tid >> 8;           // u = 0..3
#pragma unroll
    for (int h = 0; h < 2; h++) {
        __syncthreads();   // round 0: also protects the table/stage union
        if ((dl >> 1) == h) {
#pragma unroll
            for (int p = 0; p < 4; p++) {
                float* st = sm.stage + (size_t)((dl & 1) * 16 + dq * 4 + p) * 264
                          + half * 128 + l * 4;
                *reinterpret_cast<float4*>(st) =
                    make_float4(u64lo(acc[2 * p]),     u64hi(acc[2 * p]),
                                u64lo(acc[2 * p + 1]), u64hi(acc[2 * p + 1]));
            }
        }
        __syncthreads();
        // thread (c, u): line = 2h + (u&1), x-half = (u>>1)*8
        int LL = 4 * jj + 2 * h + (u & 1);
        int xo = (u >> 1) * 8;
        float* op = outp + (size_t)c * HW + LL * 256 + 16 * kk + xo;
#pragma unroll
        for (int g = 0; g < 2; g++) {
            int pb = (u & 1) * 16 + xo + 4 * g;
            float4 q = make_float4(sm.stage[(size_t)(pb + 0) * 264 + c],
                                   sm.stage[(size_t)(pb + 1) * 264 + c],
                                   sm.stage[(size_t)(pb + 2) * 264 + c],
                                   sm.stage[(size_t)(pb + 3) * 264 + c]);
            *reinterpret_cast<float4*>(op + 4 * g) = q;
        }
    }
}

extern "C" void kernel_launch(void* const* d_in, const int* in_sizes, int n_in,
                              void* d_out, int out_size) {
    const float* acc = (const float*)d_in[0];
    float* out = (float*)d_out;

    k_trig<<<1, 192>>>();
    k_transpose<<<dim3(AR / 32, NC / 32), dim3(32, 8)>>>(acc);
    k_tab<<<dim3(NS4 / 8, 2), 256>>>();       // both sorted tables, one launch
    k_pass<1><<<1024, 1024>>>(out);           // pass B -> g_pBT (pixel-major)
    k_pass<0><<<1024, 1024>>>(out);           // pass A: += pBT fold, -> out
}